// round 16
// baseline (speedup 1.0000x reference)
#include <cuda_runtime.h>
#include <cfloat>
#include <cstdint>

#define Bn 16
#define Cn 64
#define Nn 2048
#define On 64
#define Kn 20
#define CNT_TOT (16*2048*20)

// ---------------- scratch (static device globals; no runtime allocation) ----------------
__device__ float  g_D[(size_t)Bn*Nn*Nn];     // 256 MB neg_dist scratch
__device__ float  g_xx[Bn*Nn];               // squared norms
__device__ int    g_idx[Bn*Nn*Kn];           // top-K index sets (order arbitrary)
__device__ float  g_U[(size_t)Bn*Nn*On];     // U[b][m][o] = Wd . x  (o contiguous)
__device__ float  g_Bse[(size_t)Bn*Nn*On];   // (V-U)[b][n][o]
__device__ double g_sum[On], g_sumsq[On];
__device__ float  g_scale[On], g_shift[On];

// ---------------- kernel 0: zero the stats accumulators (graph replays!) ----------------
__global__ void k_zero() {
    int o = threadIdx.x;
    g_sum[o] = 0.0; g_sumsq[o] = 0.0;
}

// ---------------- kernel 1: xx[b,n] = sum_c x^2 ----------------
__global__ void k_xx(const float* __restrict__ x) {
    int id = blockIdx.x * blockDim.x + threadIdx.x;   // 0 .. B*N-1
    if (id >= Bn * Nn) return;
    int b = id / Nn, n = id % Nn;
    const float* xp = x + (size_t)b * Cn * Nn + n;
    float s = 0.f;
#pragma unroll
    for (int c = 0; c < Cn; c++) {
        float v = xp[(size_t)c * Nn];
        s = fmaf(v, v, s);
    }
    g_xx[id] = s;
}

// ---------------- kernel 2: neg_dist via tf32 mma.sync, 4-term split ----------------
// x = h + l (h = trunc13(x) is exactly tf32; l = trunc13(x-h)). inner =
// hh + hl + lh + ll MMA terms in fp32 accumulators -> error ~2^-21 relative
// (tf32 trunc of l only), far below neighbor gaps. 128x128 tile per block,
// 8 warps each 32(n) x 64(m) via m16n8k8 fragments. Triangular grid; mirror
// via smem-staged transpose.
#define GP 132                              // padded smem row stride (floats)
#define SM_AH 0
#define SM_AL (32*GP)
#define SM_BH (64*GP)
#define SM_BL (96*GP)
#define SM_XN (128*GP)
#define SM_XM (128*GP + 128)
#define SM_FLOATS (128*GP + 256)            // 17152 floats = 68608 B

static __device__ __forceinline__ float trunc13(float v) {
    return __uint_as_float(__float_as_uint(v) & 0xFFFFE000u);
}
static __device__ __forceinline__ void mma_tf32(float c[4], const unsigned a[4],
                                                unsigned b0, unsigned b1) {
    asm volatile(
        "mma.sync.aligned.m16n8k8.row.col.f32.tf32.tf32.f32 "
        "{%0,%1,%2,%3}, {%4,%5,%6,%7}, {%8,%9}, {%0,%1,%2,%3};"
        : "+f"(c[0]), "+f"(c[1]), "+f"(c[2]), "+f"(c[3])
        : "r"(a[0]), "r"(a[1]), "r"(a[2]), "r"(a[3]), "r"(b0), "r"(b1));
}

__global__ void __launch_bounds__(256, 2) k_gramtf(const float* __restrict__ x) {
    extern __shared__ __align__(16) float sh[];
    float* AhS = sh + SM_AH;
    float* AlS = sh + SM_AL;
    float* BhS = sh + SM_BH;
    float* BlS = sh + SM_BL;
    float* XN  = sh + SM_XN;
    float* XM  = sh + SM_XM;

    int t = blockIdx.x, b = blockIdx.y;
    int tm = (int)((sqrtf(8.f * t + 1.f) - 1.f) * 0.5f);
    while ((tm + 1) * (tm + 2) / 2 <= t) tm++;
    while (tm * (tm + 1) / 2 > t) tm--;
    int tn = t - tm * (tm + 1) / 2;
    int n0 = tn * 128, m0 = tm * 128;

    int tid = threadIdx.x, lane = tid & 31, warp = tid >> 5;
    int gid = lane >> 2, tid4 = lane & 3;
    const float* xb = x + (size_t)b * Cn * Nn;

    if (tid < 128) XN[tid] = g_xx[b * Nn + n0 + tid];
    else           XM[tid - 128] = g_xx[b * Nn + m0 + (tid - 128)];

    int R0 = (warp >> 1) * 32;              // n-local row base for this warp
    int CB0 = (warp & 1) * 64;              // m-local col base

    float C[2][8][4];
#pragma unroll
    for (int mt = 0; mt < 2; mt++)
#pragma unroll
        for (int nt = 0; nt < 8; nt++)
#pragma unroll
            for (int q = 0; q < 4; q++) C[mt][nt][q] = 0.f;

    for (int kc = 0; kc < 64; kc += 32) {
        __syncthreads();
#pragma unroll
        for (int i = 0; i < 16; i++) {
            int e = i * 256 + tid;
            int c = e >> 7, col = e & 127;
            float fA = xb[(size_t)(kc + c) * Nn + n0 + col];
            float fB = xb[(size_t)(kc + c) * Nn + m0 + col];
            float hA = trunc13(fA), hB = trunc13(fB);
            AhS[c * GP + col] = hA; AlS[c * GP + col] = trunc13(fA - hA);
            BhS[c * GP + col] = hB; BlS[c * GP + col] = trunc13(fB - hB);
        }
        __syncthreads();

#pragma unroll
        for (int ks = 0; ks < 4; ks++) {
            int k0 = ks * 8;
            unsigned ah[2][4], al[2][4];
#pragma unroll
            for (int mt = 0; mt < 2; mt++) {
                int R = R0 + mt * 16 + gid;
                int b1 = (k0 + tid4) * GP + R;
                int b2 = (k0 + tid4 + 4) * GP + R;
                ah[mt][0] = __float_as_uint(AhS[b1]);
                ah[mt][1] = __float_as_uint(AhS[b1 + 8]);
                ah[mt][2] = __float_as_uint(AhS[b2]);
                ah[mt][3] = __float_as_uint(AhS[b2 + 8]);
                al[mt][0] = __float_as_uint(AlS[b1]);
                al[mt][1] = __float_as_uint(AlS[b1 + 8]);
                al[mt][2] = __float_as_uint(AlS[b2]);
                al[mt][3] = __float_as_uint(AlS[b2 + 8]);
            }
#pragma unroll
            for (int nt = 0; nt < 8; nt++) {
                int CB = CB0 + nt * 8 + gid;
                int c1 = (k0 + tid4) * GP + CB;
                int c2 = (k0 + tid4 + 4) * GP + CB;
                unsigned b0h = __float_as_uint(BhS[c1]);
                unsigned b1h = __float_as_uint(BhS[c2]);
                unsigned b0l = __float_as_uint(BlS[c1]);
                unsigned b1l = __float_as_uint(BlS[c2]);
#pragma unroll
                for (int mt = 0; mt < 2; mt++) {
                    mma_tf32(C[mt][nt], ah[mt], b0h, b1h);
                    mma_tf32(C[mt][nt], ah[mt], b0l, b1l);
                    mma_tf32(C[mt][nt], al[mt], b0h, b1h);
                    mma_tf32(C[mt][nt], al[mt], b0l, b1l);
                }
            }
        }
    }

    __syncthreads();                        // tiles dead; reuse sh[0..] as stage S
    float* S = sh;                          // [128][GP]
#pragma unroll
    for (int mt = 0; mt < 2; mt++) {
        int r0 = R0 + mt * 16 + gid;
        float xn0 = XN[r0], xn8 = XN[r0 + 8];
#pragma unroll
        for (int nt = 0; nt < 8; nt++) {
            int c0 = CB0 + nt * 8 + tid4 * 2;
            float xm0 = XM[c0], xm1 = XM[c0 + 1];
            S[r0 * GP + c0]           = 2.f * C[mt][nt][0] - xn0 - xm0;
            S[r0 * GP + c0 + 1]       = 2.f * C[mt][nt][1] - xn0 - xm1;
            S[(r0 + 8) * GP + c0]     = 2.f * C[mt][nt][2] - xn8 - xm0;
            S[(r0 + 8) * GP + c0 + 1] = 2.f * C[mt][nt][3] - xn8 - xm1;
        }
    }
    __syncthreads();

    float* Db = g_D + (size_t)b * Nn * Nn;
    const float4* S4 = (const float4*)S;    // row stride GP/4 = 33 float4
#pragma unroll
    for (int q2 = 0; q2 < 16; q2++) {
        int f4 = q2 * 256 + tid;
        int row = f4 >> 5, c4 = f4 & 31;
        float4 v = S4[row * 33 + c4];
        *(float4*)&Db[(size_t)(n0 + row) * Nn + m0 + c4 * 4] = v;
    }

    if (tm != tn) {                         // mirror: D[m][n] via transposed reads
#pragma unroll
        for (int q2 = 0; q2 < 16; q2++) {
            int idx = q2 * 256 + tid;
            int mc = idx >> 5, g4 = idx & 31;
            float4 v = make_float4(S[(g4 * 4 + 0) * GP + mc],
                                   S[(g4 * 4 + 1) * GP + mc],
                                   S[(g4 * 4 + 2) * GP + mc],
                                   S[(g4 * 4 + 3) * GP + mc]);
            *(float4*)&Db[(size_t)(m0 + mc) * Nn + n0 + g4 * 4] = v;
        }
    }
}

// ---------------- kernel 3: top-K=20, TWO rows per block, MLP-4 loads ----------------
// Per row: sampled threshold -> sparse 256-bin histogram over [thr, 0];
// suffix scan; direct emit above threshold bin (only the SET matters
// downstream); exact (value desc, idx asc) rank in the threshold bin ->
// identical set to stable top_k. Degenerate rows fall back to exact iterative
// argmax with block-uniform guards. f[r][i] = element tid*8+i of row rbase+r.
__global__ void __launch_bounds__(256) k_topk2() {
    int rbase = blockIdx.x * 2;                 // rows rbase, rbase+1
    int tid = threadIdx.x, lane = tid & 31, warp = tid >> 5;

    __shared__ float s_wmax[2][8];
    __shared__ int   hist[2][257];              // suffix-scanned in place
    __shared__ int   s_c[2], s_win[2], s_kp[2], s_cnt[2], s_tb[2];
    __shared__ float          cv[2][64];
    __shared__ unsigned short cix[2][64];
    __shared__ float sv[8];
    __shared__ int   si[8];
    __shared__ int   swin;

    const float4* dA = (const float4*)(g_D + (size_t)rbase * Nn);
    const float4* dB = (const float4*)(g_D + (size_t)(rbase + 1) * Nn);
    float4 A0 = dA[tid * 2], A1 = dA[tid * 2 + 1];
    float4 B0 = dB[tid * 2], B1 = dB[tid * 2 + 1];

    float f[2][8] = {{A0.x, A0.y, A0.z, A0.w, A1.x, A1.y, A1.z, A1.w},
                     {B0.x, B0.y, B0.z, B0.w, B1.x, B1.y, B1.z, B1.w}};

    float s0 = f[0][0], s1 = f[1][0];
#pragma unroll
    for (int off = 16; off; off >>= 1) {
        s0 = fmaxf(s0, __shfl_xor_sync(0xffffffffu, s0, off));
        s1 = fmaxf(s1, __shfl_xor_sync(0xffffffffu, s1, off));
    }
    if (lane == 0) { s_wmax[0][warp] = s0; s_wmax[1][warp] = s1; }
    hist[0][tid] = 0; hist[1][tid] = 0;
    if (tid == 0) {
        hist[0][256] = 0; hist[1][256] = 0;
        s_c[0] = s_c[1] = 0; s_cnt[0] = s_cnt[1] = 0; s_tb[0] = s_tb[1] = 0;
    }
    __syncthreads();

    float thr[2]; bool fb[2]; float scl[2];
#pragma unroll
    for (int r = 0; r < 2; r++) {
        float t = s_wmax[r][0];
#pragma unroll
        for (int w = 1; w < 8; w++) t = fminf(t, s_wmax[r][w]);
        thr[r] = t;
        fb[r] = (t > -1e-20f);
        scl[r] = fb[r] ? 0.f : 255.f / (-t);
    }

    int bin[2][8];
#pragma unroll
    for (int r = 0; r < 2; r++) {
        if (!fb[r]) {
            int c = 0;
#pragma unroll
            for (int i = 0; i < 8; i++) {
                if (f[r][i] >= thr[r]) {
                    c++;
                    int bb = (int)((f[r][i] - thr[r]) * scl[r]);
                    bb = bb > 255 ? 255 : bb;
                    bin[r][i] = bb;
                    atomicAdd(&hist[r][bb], 1);
                } else bin[r][i] = -1;
            }
            c = __reduce_add_sync(0xffffffffu, c);
            if (lane == 0 && c) atomicAdd(&s_c[r], c);
        }
    }
    __syncthreads();

    bool ok[2];
#pragma unroll
    for (int r = 0; r < 2; r++) ok[r] = (!fb[r] && s_c[r] >= Kn);

    if (warp < 2 && ok[warp]) {
        int* h = hist[warp];
        int base = lane * 8, l[8], run = 0;
#pragma unroll
        for (int j = 7; j >= 0; j--) { run += h[base + j]; l[j] = run; }
        int tot = run, inc = tot;
#pragma unroll
        for (int off = 1; off < 32; off <<= 1) {
            int v = __shfl_down_sync(0xffffffffu, inc, off);
            if (lane + off < 32) inc += v;
        }
        int above = inc - tot;
#pragma unroll
        for (int j = 0; j < 8; j++) h[base + j] = l[j] + above;
    }
    __syncthreads();

#pragma unroll
    for (int r = 0; r < 2; r++) {
        if (ok[r]) {
            int cg = hist[r][tid], cgn = hist[r][tid + 1];
            if (cg >= Kn && cgn < Kn) { s_win[r] = tid; s_kp[r] = Kn - cgn; }
        }
    }
    __syncthreads();

    bool sel[2]; int win[2], kp[2];
#pragma unroll
    for (int r = 0; r < 2; r++) {
        if (ok[r]) {
            win[r] = s_win[r]; kp[r] = s_kp[r];
            int tb = hist[r][win[r]] - hist[r][win[r] + 1];
            sel[r] = (tb <= 64);
        } else { sel[r] = false; win[r] = 0; kp[r] = 0; }
    }

#pragma unroll
    for (int r = 0; r < 2; r++) {
        if (sel[r]) {
            int* op = g_idx + (rbase + r) * Kn;
#pragma unroll
            for (int i = 0; i < 8; i++) {
                if (bin[r][i] > win[r]) {
                    op[atomicAdd(&s_cnt[r], 1)] = tid * 8 + i;
                } else if (bin[r][i] == win[r]) {
                    int q = atomicAdd(&s_tb[r], 1);
                    cv[r][q] = f[r][i]; cix[r][q] = (unsigned short)(tid * 8 + i);
                }
            }
        }
    }
    __syncthreads();

#pragma unroll
    for (int r = 0; r < 2; r++) {
        if (sel[r]) {
            int cc = s_tb[r], base = s_cnt[r];
            int* op = g_idx + (rbase + r) * Kn;
            for (int i = tid; i < cc; i += 256) {
                float vi = cv[r][i]; int xi = cix[r][i];
                int rk = 0;
                for (int j = 0; j < cc; j++) {
                    float vj = cv[r][j];
                    rk += (vj > vi) || (vj == vi && cix[r][j] < xi);
                }
                if (rk < kp[r]) op[base + rk] = xi;
            }
        }
    }

#pragma unroll
    for (int r = 0; r < 2; r++) {
        if (!sel[r]) {                           // block-uniform
            __syncthreads();
            int* op = g_idx + (rbase + r) * Kn;
            float g[8];
#pragma unroll
            for (int i = 0; i < 8; i++) g[i] = f[r][i];
            for (int k = 0; k < Kn; k++) {
                float bv = -FLT_MAX;
                int   bi = 0x7fffffff;
#pragma unroll
                for (int i = 0; i < 8; i++) {
                    int e = tid * 8 + i;
                    if (g[i] > bv) { bv = g[i]; bi = e; }
                }
#pragma unroll
                for (int off = 16; off; off >>= 1) {
                    float ov = __shfl_down_sync(0xffffffffu, bv, off);
                    int   oi = __shfl_down_sync(0xffffffffu, bi, off);
                    if (ov > bv || (ov == bv && oi < bi)) { bv = ov; bi = oi; }
                }
                if (lane == 0) { sv[warp] = bv; si[warp] = bi; }
                __syncthreads();
                if (tid == 0) {
                    float fv = sv[0]; int fi = si[0];
#pragma unroll
                    for (int w = 1; w < 8; w++)
                        if (sv[w] > fv || (sv[w] == fv && si[w] < fi)) { fv = sv[w]; fi = si[w]; }
                    swin = fi;
                    op[k] = fi;
                }
                __syncthreads();
                int w = swin;
                if ((w >> 3) == tid) g[w & 7] = -FLT_MAX;
            }
        }
    }
}

// ---------------- kernel 4: U = Wd.x , Bse = (Wc-Wd).x  (o-contiguous layout) -----------
__global__ void k_uv(const float* __restrict__ x, const float* __restrict__ W) {
    int b = blockIdx.y;
    int m0 = blockIdx.x * 64;
    __shared__ float Wd[64 * 64];   // [c][o]
    __shared__ float Wf[64 * 64];   // [c][o]  (Wc - Wd)
    __shared__ float xs[64 * 64];   // [c][m]
    int tid = threadIdx.x;
#pragma unroll
    for (int i = 0; i < 16; i++) {
        int id = tid + 256 * i;
        int o = id >> 6, c = id & 63;
        float wd = W[o * 128 + c];
        float wc = W[o * 128 + 64 + c];
        Wd[c * 64 + o] = wd;
        Wf[c * 64 + o] = wc - wd;
        xs[id] = x[(size_t)b * Cn * Nn + (size_t)(id >> 6) * Nn + m0 + (id & 63)];
    }
    __syncthreads();

    int o = tid & 63, mq = tid >> 6;
    float aU[16], aD[16];
#pragma unroll
    for (int t = 0; t < 16; t++) { aU[t] = 0.f; aD[t] = 0.f; }

    for (int c = 0; c < 64; c++) {
        float wu = Wd[c * 64 + o];
        float wf = Wf[c * 64 + o];
#pragma unroll
        for (int t = 0; t < 16; t++) {
            float xv = xs[c * 64 + mq + t * 4];   // broadcast within warp
            aU[t] = fmaf(wu, xv, aU[t]);
            aD[t] = fmaf(wf, xv, aD[t]);
        }
    }
#pragma unroll
    for (int t = 0; t < 16; t++) {
        int m = m0 + mq + t * 4;
        g_U  [((size_t)b * Nn + m) * On + o] = aU[t];
        g_Bse[((size_t)b * Nn + m) * On + o] = aD[t];
    }
}

// ---------------- kernel 5: per-channel sum / sumsq of y over (b,n,k) ----------------
__global__ void k_stats() {
    int b = blockIdx.y;
    int n0 = blockIdx.x * 128;
    int tid = threadIdx.x;
    int o = tid & 63, g = tid >> 6;
    float s = 0.f, s2 = 0.f;
    for (int j = 0; j < 32; j++) {
        int n = n0 + g * 32 + j;
        float bse = g_Bse[((size_t)b * Nn + n) * On + o];
        const int* ip = g_idx + (b * Nn + n) * Kn;
#pragma unroll
        for (int k = 0; k < Kn; k++) {
            int m = ip[k];
            float y = g_U[((size_t)b * Nn + m) * On + o] + bse;
            s += y;
            s2 = fmaf(y, y, s2);
        }
    }
    __shared__ float ss[4][64], ss2[4][64];
    ss[g][o] = s; ss2[g][o] = s2;
    __syncthreads();
    if (g == 0) {
        double ts = (double)ss[0][o] + (double)ss[1][o] + (double)ss[2][o] + (double)ss[3][o];
        double t2 = (double)ss2[0][o] + (double)ss2[1][o] + (double)ss2[2][o] + (double)ss2[3][o];
        atomicAdd(&g_sum[o], ts);
        atomicAdd(&g_sumsq[o], t2);
    }
}

// ---------------- kernel 6: finalize BN affine ----------------
__global__ void k_fin(const float* __restrict__ gamma, const float* __restrict__ beta) {
    int o = threadIdx.x;
    double mean = g_sum[o] / (double)CNT_TOT;
    double var  = g_sumsq[o] / (double)CNT_TOT - mean * mean;
    float sc = gamma[o] * rsqrtf((float)var + 1e-5f);
    g_scale[o] = sc;
    g_shift[o] = beta[o] - (float)mean * sc;
}

// ---------------- kernel 7: normalize + leaky relu + max over k -> out[b][o][n] --------
__global__ void k_out(float* __restrict__ out) {
    int b = blockIdx.y;
    int n0 = blockIdx.x * 32;
    int tid = threadIdx.x;
    int o = tid & 63, nq = tid >> 6;
    __shared__ float sm[64 * 33];
    float sc = g_scale[o], sh = g_shift[o];
    for (int j = 0; j < 8; j++) {
        int nl = nq * 8 + j;
        int n = n0 + nl;
        float bse = g_Bse[((size_t)b * Nn + n) * On + o];
        const int* ip = g_idx + (b * Nn + n) * Kn;
        float mx = -FLT_MAX;
#pragma unroll
        for (int k = 0; k < Kn; k++) {
            int m = ip[k];
            float y  = g_U[((size_t)b * Nn + m) * On + o] + bse;
            float yn = fmaf(y, sc, sh);
            float a  = (yn >= 0.f) ? yn : 0.2f * yn;
            mx = fmaxf(mx, a);
        }
        sm[o * 33 + nl] = mx;
    }
    __syncthreads();
    int nl2 = tid & 31, og = tid >> 5;
#pragma unroll
    for (int j = 0; j < 8; j++) {
        int o2 = og * 8 + j;
        out[((size_t)b * On + o2) * Nn + n0 + nl2] = sm[o2 * 33 + nl2];
    }
}

// ---------------- launch ----------------
extern "C" void kernel_launch(void* const* d_in, const int* in_sizes, int n_in,
                              void* d_out, int out_size) {
    const float* x     = (const float*)d_in[0];
    const float* W     = (const float*)d_in[1];
    const float* gamma = (const float*)d_in[2];
    const float* beta  = (const float*)d_in[3];
    float* out = (float*)d_out;

    cudaFuncSetAttribute(k_gramtf, cudaFuncAttributeMaxDynamicSharedMemorySize,
                         SM_FLOATS * (int)sizeof(float));

    k_zero<<<1, 64>>>();
    k_xx<<<(Bn * Nn) / 256, 256>>>(x);

    dim3 gg(136, 16);                 // triangular tile set, 128x128 tiles
    k_gramtf<<<gg, 256, SM_FLOATS * sizeof(float)>>>(x);

    k_topk2<<<(Bn * Nn) / 2, 256>>>();

    dim3 guv(Nn / 64, Bn);
    k_uv<<<guv, 256>>>(x, W);

    dim3 gst(16, Bn);
    k_stats<<<gst, 256>>>();

    k_fin<<<1, 64>>>(gamma, beta);

    dim3 go(Nn / 32, Bn);
    k_out<<<go, 256>>>(out);
}